// round 15
// baseline (speedup 1.0000x reference)
#include <cuda_runtime.h>
#include <cuda_fp16.h>
#include <cstdint>

// y[64,4096] = x[64,11008] @ dequant(W)[4096,11008]^T + bias
// mma.sync.m16n8k16 f16/fp32, barrier-free. W: coalesced LDG.128 (evict_first)
// + quad byte transpose -> f16x2 dequant (LOP3/prmt + exact sub.f16x2 + hfma2).
// AB coeffs packed f16 pairs (4B). x pre-packed A-fragments (evict_last).
// CTA = 64 thr (2 warps x n32). Grid: 64 o-tiles x KSPLIT(8) = 512 CTAs.

#define OUT_F  4096
#define IN_F   11008
#define MROWS  64
#define KSPLIT 8
#define KC     (IN_F / KSPLIT)     // 1376
#define NSTEP  (KC / 32)           // 43
#define NSUB   (IN_F / 32)         // 344
#define NKT    (IN_F / 16)         // 688
#define XBLKS  86                  // prep: xfrag blocks (8 ktiles each)

__device__ float  g_part[KSPLIT][MROWS * OUT_F];        // 8 MB
__device__ __align__(16) uint4    g_xfrag[NKT * 4 * 32];// 1.4 MB A-fragments
__device__ __align__(16) uint32_t g_ab2[NSUB * OUT_F];  // 5.6 MB f16 (A,B)

__device__ __forceinline__ uint32_t pkh2(float lo, float hi) {
    uint32_t r;
    asm("cvt.rn.f16x2.f32 %0, %1, %2;" : "=r"(r) : "f"(hi), "f"(lo));
    return r;
}
__device__ __forceinline__ void mma16816(float* c, const uint32_t* a,
                                         uint32_t b0, uint32_t b1) {
    asm volatile(
        "mma.sync.aligned.m16n8k16.row.col.f32.f16.f16.f32 "
        "{%0,%1,%2,%3}, {%4,%5,%6,%7}, {%8,%9}, {%0,%1,%2,%3};"
        : "+f"(c[0]), "+f"(c[1]), "+f"(c[2]), "+f"(c[3])
        : "r"(a[0]), "r"(a[1]), "r"(a[2]), "r"(a[3]), "r"(b0), "r"(b1));
}
__device__ __forceinline__ uint4 ldg_x(const uint4* p) {     // keep in L1
    uint4 v;
    asm volatile("ld.global.nc.L1::evict_last.v4.u32 {%0,%1,%2,%3}, [%4];"
                 : "=r"(v.x), "=r"(v.y), "=r"(v.z), "=r"(v.w) : "l"(p));
    return v;
}
__device__ __forceinline__ int4 ldg_w(const int* p) {        // streaming
    int4 v;
    asm volatile("ld.global.nc.L1::evict_first.v4.u32 {%0,%1,%2,%3}, [%4];"
                 : "=r"(v.x), "=r"(v.y), "=r"(v.z), "=r"(v.w) : "l"(p));
    return v;
}
__device__ __forceinline__ uint32_t ldg_ab(const uint32_t* p) {
    uint32_t v;
    asm volatile("ld.global.nc.L1::evict_first.u32 %0, [%1];" : "=r"(v) : "l"(p));
    return v;
}
__device__ __forceinline__ uint32_t hsub2u(uint32_t a, uint32_t b) {
    uint32_t r; asm("sub.rn.f16x2 %0, %1, %2;" : "=r"(r) : "r"(a), "r"(b));
    return r;
}
__device__ __forceinline__ uint32_t hfma2u(uint32_t a, uint32_t b, uint32_t c) {
    uint32_t r;
    asm("fma.rn.f16x2 %0, %1, %2, %3;" : "=r"(r) : "r"(a), "r"(b), "r"(c));
    return r;
}

struct WB {                   // prefetched W data for one k32 step
    int4     wv[4];           // raw packed int32s, one int4 per n8 group
    uint32_t ab[4];           // packed f16 (A, B) per n8 group
};

__global__ __launch_bounds__(64, 4)
void qmma_kernel(const int* __restrict__ packed)
{
    const int t    = threadIdx.x;
    const int lane = t & 31;
    const int w    = t >> 5;                 // 2 warps, n32 each
    const int ob   = blockIdx.x & 63;        // 64-wide o tile
    const int ks   = blockIdx.x >> 6;
    const int o0w  = ob * 64 + w * 32;
    const int kbase = ks * KC;

    const int q  = lane & 3;                 // quad index
    const int rq = lane >> 2;                // row-in-group 0..7

    const uint32_t selA = 0x40 + q * 0x11;
    const uint32_t selR = (q & 1) ? ((q & 2) ? 0x0145u : 0x4501u)
                                  : ((q & 2) ? 0x1054u : 0x5410u);

    const int* prow[4];
#pragma unroll
    for (int nt = 0; nt < 4; nt++)
        prow[nt] = packed + (o0w + 8 * nt + rq) * (IN_F / 2) + (kbase >> 1) + q * 4;
    const uint32_t* abp = g_ab2 + (size_t)(ks * NSTEP) * OUT_F + o0w + rq;
    const uint4* xfl = g_xfrag + lane;
    const int kt0 = (kbase >> 4);

    float acc[4][4][4];
#pragma unroll
    for (int mt = 0; mt < 4; mt++)
#pragma unroll
        for (int nt = 0; nt < 4; nt++)
#pragma unroll
            for (int i = 0; i < 4; i++) acc[mt][nt][i] = 0.f;

    auto LOADW = [&](int s, WB& v) {
#pragma unroll
        for (int nt = 0; nt < 4; nt++)
            v.wv[nt] = ldg_w(prow[nt] + s * 16);
#pragma unroll
        for (int nt = 0; nt < 4; nt++)
            v.ab[nt] = ldg_ab(abp + (size_t)s * OUT_F + 8 * nt);
    };
    auto LOADX = [&](int s, uint4* xv) {
        const int kt = kt0 + s * 2;
#pragma unroll
        for (int i = 0; i < 8; i++)
            xv[i] = ldg_x(xfl + ((kt + (i >> 2)) * 4 + (i & 3)) * 32);
    };

    auto STEP = [&](int s, WB& wv, uint4* xv) {
        uint32_t h[4][4];
#pragma unroll
        for (int nt = 0; nt < 4; nt++) {
            const int4 v = wv.wv[nt];
            const uint32_t t01 = __byte_perm(v.x, v.y, 0x0040);
            const uint32_t t23 = __byte_perm(v.z, v.w, 0x0040);
            const uint32_t P   = __byte_perm(t01, t23, 0x5410);
            const uint32_t S1 = __shfl_xor_sync(0xffffffffu, P, 1);
            const uint32_t S2 = __shfl_xor_sync(0xffffffffu, P, 2);
            const uint32_t S3 = __shfl_xor_sync(0xffffffffu, P, 3);
            const uint32_t mA = __byte_perm(P,  S1, selA);
            const uint32_t mB = __byte_perm(S2, S3, selA);
            const uint32_t R  = __byte_perm(mA, mB, selR);
            const uint32_t A2 = __byte_perm(wv.ab[nt], wv.ab[nt], 0x1010);
            const uint32_t B2 = __byte_perm(wv.ab[nt], wv.ab[nt], 0x3232);
#pragma unroll
            for (int j = 0; j < 4; j++) {
                const uint32_t u1 = ((R >> (8 * j))     & 15u) | 0x6400u;
                const uint32_t u2 = ((R >> (8 * j + 4)) & 15u) | 0x6400u;
                const uint32_t q32 = __byte_perm(u1, u2, 0x5410);
                const uint32_t qh  = hsub2u(q32, 0x64006400u);  // exact
                h[nt][j] = hfma2u(qh, A2, B2);                  // one rounding
            }
        }
        if (s + 2 < NSTEP) LOADW(s + 2, wv);   // early: latency cover
#pragma unroll
        for (int tt = 0; tt < 2; tt++)
#pragma unroll
            for (int mt = 0; mt < 4; mt++) {
                const uint32_t* a = (const uint32_t*)&xv[tt * 4 + mt];
#pragma unroll
                for (int nt = 0; nt < 4; nt++)
                    mma16816(acc[mt][nt], a, h[nt][2 * tt], h[nt][2 * tt + 1]);
            }
        if (s + 2 < NSTEP) LOADX(s + 2, xv);
    };

    WB wa, wb;
    uint4 xa[8], xb[8];
    LOADW(0, wa); LOADX(0, xa);
    LOADW(1, wb); LOADX(1, xb);

#pragma unroll 1
    for (int s = 0; s < NSTEP - 1; s += 2) {
        STEP(s, wa, xa);
        STEP(s + 1, wb, xb);
    }
    STEP(NSTEP - 1, wa, xa);     // NSTEP odd: final step uses buffer a

    float* part = g_part[ks];
#pragma unroll
    for (int mt = 0; mt < 4; mt++) {
        const int m = mt * 16 + rq;
#pragma unroll
        for (int nt = 0; nt < 4; nt++) {
            const int n = o0w + nt * 8 + q * 2;
            *(float2*)&part[m * OUT_F + n] =
                make_float2(acc[mt][nt][0], acc[mt][nt][1]);
            *(float2*)&part[(m + 8) * OUT_F + n] =
                make_float2(acc[mt][nt][2], acc[mt][nt][3]);
        }
    }
}

// merged prep: blocks [0, XBLKS) pack x into A-fragment layout via smem;
// blocks [XBLKS, ...) fold scales into g_ab2 (packed f16) via smem transpose.
__global__ __launch_bounds__(256)
void prep_kernel(const float* __restrict__ x,
                 const float* __restrict__ d,
                 const float* __restrict__ dmin,
                 const int*   __restrict__ scales,
                 const int*   __restrict__ mins)
{
    __shared__ __align__(16) char sbuf[64 * 68 * 4];   // 17.4 KB, both roles
    const int t = threadIdx.x;

    if (blockIdx.x < XBLKS) {
        // xfrag: block covers 8 ktiles = 128 columns, all 64 rows
        uint32_t (*smu)[68] = (uint32_t(*)[68])sbuf;
        const int b = blockIdx.x;
        const float* xb = x + b * 128;
#pragma unroll
        for (int i = 0; i < 8; i++) {
            const int idx = t + i * 256;
            const int row = idx >> 5, c4 = idx & 31;
            const float4 v = *(const float4*)(xb + row * IN_F + c4 * 4);
            smu[row][c4 * 2]     = pkh2(v.x, v.y);
            smu[row][c4 * 2 + 1] = pkh2(v.z, v.w);
        }
        __syncthreads();
        uint4* outp = g_xfrag + b * (8 * 4 * 32);
#pragma unroll
        for (int i = 0; i < 4; i++) {
            const int idx  = t + i * 256;
            const int lane = idx & 31;
            const int mt   = (idx >> 5) & 3;
            const int ktl  = idx >> 7;
            const int r  = mt * 16 + (lane >> 2);
            const int ch = ktl * 8 + (lane & 3);
            outp[idx] = make_uint4(smu[r][ch],     smu[r + 8][ch],
                                   smu[r][ch + 4], smu[r + 8][ch + 4]);
        }
    } else {
        // AB: block = 64 rows x 8 subs, packed f16 output [sub][row]
        uint32_t (*tile)[66] = (uint32_t(*)[66])sbuf;
        const int bb = blockIdx.x - XBLKS;
        const int r0 = (bb & 63) * 64;        // row tile (64 rows)
        const int s0 = (bb >> 6) * 8;         // sub tile (8 subs)
        {
            const int lr = t >> 3, lsu = t & 7;
#pragma unroll
            for (int half = 0; half < 2; half++) {
                const int row = r0 + lr + half * 32;
                const int si  = row * NSUB + (s0 + lsu);
                const float dd = __ldg(d + (si >> 3));
                const float dm = __ldg(dmin + (si >> 3));
                const float A = dd * (float)__ldg(scales + si) * (1.f / 945.f);
                const float B = fmaf(dd, (float)__ldg(mins + si) * (1.f / 63.f), dm);
                tile[lsu][lr + half * 32] = pkh2(A, B);   // (A_f16, B_f16)
            }
        }
        __syncthreads();
        {
#pragma unroll
            for (int half = 0; half < 2; half++) {
                const int idx = t + half * 256;
                const int lsu = idx >> 6, lr = idx & 63;
                g_ab2[(size_t)(s0 + lsu) * OUT_F + r0 + lr] = tile[lsu][lr];
            }
        }
    }
}

__global__ __launch_bounds__(128)
void reduce_kernel(const float* __restrict__ bias, float* __restrict__ out)
{
    const int i = blockIdx.x * 128 + threadIdx.x;      // float4 index
    const float4 bb = ((const float4*)bias)[i & (OUT_F / 4 - 1)];
    float4 s = bb;
#pragma unroll
    for (int ks = 0; ks < KSPLIT; ks++) {
        const float4 p = ((const float4*)g_part[ks])[i];
        s.x += p.x; s.y += p.y; s.z += p.z; s.w += p.w;
    }
    ((float4*)out)[i] = s;
}

extern "C" void kernel_launch(void* const* d_in, const int* in_sizes, int n_in,
                              void* d_out, int out_size)
{
    const float* x      = (const float*)d_in[0];
    const int*   packed = (const int*)  d_in[1];
    const float* d      = (const float*)d_in[2];
    const float* dmin   = (const float*)d_in[3];
    const int*   scales = (const int*)  d_in[4];
    const int*   mins   = (const int*)  d_in[5];
    const float* bias   = (const float*)d_in[6];
    float* out = (float*)d_out;

    prep_kernel<<<XBLKS + (OUT_F / 64) * (NSUB / 8), 256>>>(x, d, dmin, scales, mins);
    qmma_kernel<<<64 * KSPLIT, 64>>>(packed);
    reduce_kernel<<<(MROWS * OUT_F / 4) / 128, 128>>>(bias, out);
}

// round 16
// speedup vs baseline: 1.4078x; 1.4078x over previous
#include <cuda_runtime.h>
#include <cuda_fp16.h>
#include <cstdint>

// y[64,4096] = x[64,11008] @ dequant(W)[4096,11008]^T + bias
// mma.sync.m16n8k16 f16/fp32, barrier-free. W: coalesced LDG.128 (evict_first)
// + quad byte transpose -> f16x2 dequant (exact sub.f16x2 + hfma2).
// AB coeffs packed f16 pairs. x pre-packed A-fragments (evict_last, shared by
// 4 warps/CTA through L1). Grid: 32 o-tiles x KSPLIT(8) = 256 CTAs x 128 thr.

#define OUT_F  4096
#define IN_F   11008
#define MROWS  64
#define KSPLIT 8
#define KC     (IN_F / KSPLIT)     // 1376
#define NSTEP  (KC / 32)           // 43
#define NSUB   (IN_F / 32)         // 344
#define NSUP   (IN_F / 256)        // 43 supers per row
#define NKT    (IN_F / 16)         // 688
#define XBLKS  86                  // prep: xfrag blocks (8 ktiles each)
#define ABBLKS ((OUT_F / 32) * NSUP / 8)   // 688 AB blocks (8 warps each)

__device__ float  g_part[KSPLIT][MROWS * OUT_F];        // 8 MB
__device__ __align__(16) uint4    g_xfrag[NKT * 4 * 32];// 1.4 MB A-fragments
__device__ __align__(16) uint32_t g_ab2[NSUB * OUT_F];  // 5.6 MB f16 (A,B)

__device__ __forceinline__ uint32_t pkh2(float lo, float hi) {
    uint32_t r;
    asm("cvt.rn.f16x2.f32 %0, %1, %2;" : "=r"(r) : "f"(hi), "f"(lo));
    return r;
}
__device__ __forceinline__ void mma16816(float* c, const uint32_t* a,
                                         uint32_t b0, uint32_t b1) {
    asm volatile(
        "mma.sync.aligned.m16n8k16.row.col.f32.f16.f16.f32 "
        "{%0,%1,%2,%3}, {%4,%5,%6,%7}, {%8,%9}, {%0,%1,%2,%3};"
        : "+f"(c[0]), "+f"(c[1]), "+f"(c[2]), "+f"(c[3])
        : "r"(a[0]), "r"(a[1]), "r"(a[2]), "r"(a[3]), "r"(b0), "r"(b1));
}
__device__ __forceinline__ uint4 ldg_x(const uint4* p) {     // keep in L1
    uint4 v;
    asm volatile("ld.global.nc.L1::evict_last.v4.u32 {%0,%1,%2,%3}, [%4];"
                 : "=r"(v.x), "=r"(v.y), "=r"(v.z), "=r"(v.w) : "l"(p));
    return v;
}
__device__ __forceinline__ int4 ldg_w(const int* p) {        // streaming
    int4 v;
    asm volatile("ld.global.nc.L1::evict_first.v4.u32 {%0,%1,%2,%3}, [%4];"
                 : "=r"(v.x), "=r"(v.y), "=r"(v.z), "=r"(v.w) : "l"(p));
    return v;
}
__device__ __forceinline__ uint32_t ldg_ab(const uint32_t* p) {
    uint32_t v;
    asm volatile("ld.global.nc.L1::evict_first.u32 %0, [%1];" : "=r"(v) : "l"(p));
    return v;
}
__device__ __forceinline__ uint32_t hsub2u(uint32_t a, uint32_t b) {
    uint32_t r; asm("sub.rn.f16x2 %0, %1, %2;" : "=r"(r) : "r"(a), "r"(b));
    return r;
}
__device__ __forceinline__ uint32_t hfma2u(uint32_t a, uint32_t b, uint32_t c) {
    uint32_t r;
    asm("fma.rn.f16x2 %0, %1, %2, %3;" : "=r"(r) : "r"(a), "r"(b), "r"(c));
    return r;
}

struct WB {                   // prefetched W data for one k32 step
    int4     wv[4];           // raw packed int32s, one int4 per n8 group
    uint32_t ab[4];           // packed f16 (A, B) per n8 group
};

__global__ __launch_bounds__(128, 2)
void qmma_kernel(const int* __restrict__ packed)
{
    const int t    = threadIdx.x;
    const int lane = t & 31;
    const int w    = t >> 5;                 // 4 warps, n32 each
    const int ob   = blockIdx.x & 31;        // 128-wide o tile
    const int ks   = blockIdx.x >> 5;
    const int o0w  = ob * 128 + w * 32;
    const int kbase = ks * KC;

    const int q  = lane & 3;                 // quad index
    const int rq = lane >> 2;                // row-in-group 0..7

    const uint32_t selA = 0x40 + q * 0x11;
    const uint32_t selR = (q & 1) ? ((q & 2) ? 0x0145u : 0x4501u)
                                  : ((q & 2) ? 0x1054u : 0x5410u);

    const int* prow[4];
#pragma unroll
    for (int nt = 0; nt < 4; nt++)
        prow[nt] = packed + (o0w + 8 * nt + rq) * (IN_F / 2) + (kbase >> 1) + q * 4;
    const uint32_t* abp = g_ab2 + (size_t)(ks * NSTEP) * OUT_F + o0w + rq;
    const uint4* xfl = g_xfrag + lane;
    const int kt0 = (kbase >> 4);

    float acc[4][4][4];
#pragma unroll
    for (int mt = 0; mt < 4; mt++)
#pragma unroll
        for (int nt = 0; nt < 4; nt++)
#pragma unroll
            for (int i = 0; i < 4; i++) acc[mt][nt][i] = 0.f;

    auto LOADW = [&](int s, WB& v) {
#pragma unroll
        for (int nt = 0; nt < 4; nt++)
            v.wv[nt] = ldg_w(prow[nt] + s * 16);
#pragma unroll
        for (int nt = 0; nt < 4; nt++)
            v.ab[nt] = ldg_ab(abp + (size_t)s * OUT_F + 8 * nt);
    };
    auto LOADX = [&](int s, uint4* xv) {
        const int kt = kt0 + s * 2;
#pragma unroll
        for (int i = 0; i < 8; i++)
            xv[i] = ldg_x(xfl + ((kt + (i >> 2)) * 4 + (i & 3)) * 32);
    };

    auto STEP = [&](int s, WB& wv, uint4* xv) {
        uint32_t h[4][4];
#pragma unroll
        for (int nt = 0; nt < 4; nt++) {
            const int4 v = wv.wv[nt];
            const uint32_t t01 = __byte_perm(v.x, v.y, 0x0040);
            const uint32_t t23 = __byte_perm(v.z, v.w, 0x0040);
            const uint32_t P   = __byte_perm(t01, t23, 0x5410);
            const uint32_t S1 = __shfl_xor_sync(0xffffffffu, P, 1);
            const uint32_t S2 = __shfl_xor_sync(0xffffffffu, P, 2);
            const uint32_t S3 = __shfl_xor_sync(0xffffffffu, P, 3);
            const uint32_t mA = __byte_perm(P,  S1, selA);
            const uint32_t mB = __byte_perm(S2, S3, selA);
            const uint32_t R  = __byte_perm(mA, mB, selR);
            const uint32_t A2 = __byte_perm(wv.ab[nt], wv.ab[nt], 0x1010);
            const uint32_t B2 = __byte_perm(wv.ab[nt], wv.ab[nt], 0x3232);
#pragma unroll
            for (int j = 0; j < 4; j++) {
                const uint32_t u1 = ((R >> (8 * j))     & 15u) | 0x6400u;
                const uint32_t u2 = ((R >> (8 * j + 4)) & 15u) | 0x6400u;
                const uint32_t q32 = __byte_perm(u1, u2, 0x5410);
                const uint32_t qh  = hsub2u(q32, 0x64006400u);  // exact
                h[nt][j] = hfma2u(qh, A2, B2);                  // one rounding
            }
        }
        if (s + 2 < NSTEP) LOADW(s + 2, wv);   // early: latency cover
#pragma unroll
        for (int tt = 0; tt < 2; tt++)
#pragma unroll
            for (int mt = 0; mt < 4; mt++) {
                const uint32_t* a = (const uint32_t*)&xv[tt * 4 + mt];
#pragma unroll
                for (int nt = 0; nt < 4; nt++)
                    mma16816(acc[mt][nt], a, h[nt][2 * tt], h[nt][2 * tt + 1]);
            }
        if (s + 2 < NSTEP) LOADX(s + 2, xv);
    };

    WB wa, wb;
    uint4 xa[8], xb[8];
    LOADW(0, wa); LOADX(0, xa);
    LOADW(1, wb); LOADX(1, xb);

#pragma unroll 1
    for (int s = 0; s < NSTEP - 1; s += 2) {
        STEP(s, wa, xa);
        STEP(s + 1, wb, xb);
    }
    STEP(NSTEP - 1, wa, xa);     // NSTEP odd: final step uses buffer a

    float* part = g_part[ks];
#pragma unroll
    for (int mt = 0; mt < 4; mt++) {
        const int m = mt * 16 + rq;
#pragma unroll
        for (int nt = 0; nt < 4; nt++) {
            const int n = o0w + nt * 8 + q * 2;
            *(float2*)&part[m * OUT_F + n] =
                make_float2(acc[mt][nt][0], acc[mt][nt][1]);
            *(float2*)&part[(m + 8) * OUT_F + n] =
                make_float2(acc[mt][nt][2], acc[mt][nt][3]);
        }
    }
}

// merged prep:
//  blocks [0, XBLKS): pack x into A-fragment layout via smem.
//  blocks [XBLKS, XBLKS+ABBLKS): AB gen, warp = (32-row block, one super).
//    Lane reads its row's whole super (32B scales + 32B mins, sector-perfect),
//    writes 8 coalesced 128B lines into g_ab2[sub][row].
__global__ __launch_bounds__(256)
void prep_kernel(const float* __restrict__ x,
                 const float* __restrict__ d,
                 const float* __restrict__ dmin,
                 const int*   __restrict__ scales,
                 const int*   __restrict__ mins)
{
    const int t = threadIdx.x;

    if (blockIdx.x < XBLKS) {
        __shared__ __align__(16) uint32_t smu[64][68];
        const int b = blockIdx.x;
        const float* xb = x + b * 128;
#pragma unroll
        for (int i = 0; i < 8; i++) {
            const int idx = t + i * 256;
            const int row = idx >> 5, c4 = idx & 31;
            const float4 v = *(const float4*)(xb + row * IN_F + c4 * 4);
            smu[row][c4 * 2]     = pkh2(v.x, v.y);
            smu[row][c4 * 2 + 1] = pkh2(v.z, v.w);
        }
        __syncthreads();
        uint4* outp = g_xfrag + b * (8 * 4 * 32);
#pragma unroll
        for (int i = 0; i < 4; i++) {
            const int idx  = t + i * 256;
            const int lane = idx & 31;
            const int mt   = (idx >> 5) & 3;
            const int ktl  = idx >> 7;
            const int r  = mt * 16 + (lane >> 2);
            const int ch = ktl * 8 + (lane & 3);
            outp[idx] = make_uint4(smu[r][ch],     smu[r + 8][ch],
                                   smu[r][ch + 4], smu[r + 8][ch + 4]);
        }
    } else {
        const int g    = (blockIdx.x - XBLKS) * 8 + (t >> 5);  // global warp
        const int lane = t & 31;
        const int rb   = g & 127;            // 32-row block
        const int sp   = g >> 7;             // super-in-row 0..42
        const int row  = rb * 32 + lane;

        const int si = row * NSUB + sp * 8;
        const int4 sc0 = __ldg((const int4*)(scales + si));
        const int4 sc1 = __ldg((const int4*)(scales + si + 4));
        const int4 mn0 = __ldg((const int4*)(mins + si));
        const int4 mn1 = __ldg((const int4*)(mins + si + 4));
        const float dd = __ldg(d + row * NSUP + sp);
        const float dm = __ldg(dmin + row * NSUP + sp);
        const float dA = dd * (1.f / 945.f);

        const int scv[8] = { sc0.x, sc0.y, sc0.z, sc0.w, sc1.x, sc1.y, sc1.z, sc1.w };
        const int mnv[8] = { mn0.x, mn0.y, mn0.z, mn0.w, mn1.x, mn1.y, mn1.z, mn1.w };
        uint32_t* outp = g_ab2 + (size_t)(sp * 8) * OUT_F + row;
#pragma unroll
        for (int j = 0; j < 8; j++) {
            const float A = dA * (float)scv[j];
            const float B = fmaf(dd, (float)mnv[j] * (1.f / 63.f), dm);
            outp[(size_t)j * OUT_F] = pkh2(A, B);
        }
    }
}

__global__ __launch_bounds__(128)
void reduce_kernel(const float* __restrict__ bias, float* __restrict__ out)
{
    const int i = blockIdx.x * 128 + threadIdx.x;      // float4 index
    const float4 bb = ((const float4*)bias)[i & (OUT_F / 4 - 1)];
    float4 s = bb;
#pragma unroll
    for (int ks = 0; ks < KSPLIT; ks++) {
        const float4 p = ((const float4*)g_part[ks])[i];
        s.x += p.x; s.y += p.y; s.z += p.z; s.w += p.w;
    }
    ((float4*)out)[i] = s;
}

extern "C" void kernel_launch(void* const* d_in, const int* in_sizes, int n_in,
                              void* d_out, int out_size)
{
    const float* x      = (const float*)d_in[0];
    const int*   packed = (const int*)  d_in[1];
    const float* d      = (const float*)d_in[2];
    const float* dmin   = (const float*)d_in[3];
    const int*   scales = (const int*)  d_in[4];
    const int*   mins   = (const int*)  d_in[5];
    const float* bias   = (const float*)d_in[6];
    float* out = (float*)d_out;

    prep_kernel<<<XBLKS + ABBLKS, 256>>>(x, d, dmin, scales, mins);
    qmma_kernel<<<32 * KSPLIT, 128>>>(packed);
    reduce_kernel<<<(MROWS * OUT_F / 4) / 128, 128>>>(bias, out);
}